// round 15
// baseline (speedup 1.0000x reference)
#include <cuda_runtime.h>
#include <cuda_fp16.h>
#include <cuda_bf16.h>

// Problem constants (fixed by reference setup_inputs)
#define BB 8
#define NN 1024
#define BN 8192          // B*N
#define INF 128
#define OUTF 256
#define NH 4
#define DD 64

// Scratch (device globals)
__device__ __half g_h16[BN * OUTF];     // h in fp16 (MMA B operand)
__device__ __half g_Eih[NH * BN];       // e^{s_i}
__device__ __half g_Fih[NH * BN];       // e^{0.2 s_i}
__device__ __half g_Ejh[NH * BN];       // e^{s_j}
__device__ __half g_Fjh[NH * BN];       // e^{0.2 s_j}

// cp.async helpers
__device__ __forceinline__ void cp16(unsigned dst, const void* src) {
    asm volatile("cp.async.cg.shared.global [%0], [%1], 16;" :: "r"(dst), "l"(src));
}
__device__ __forceinline__ void cp_commit() {
    asm volatile("cp.async.commit_group;");
}

// f16x2-as-u32 helpers
__device__ __forceinline__ unsigned u_hmul2(unsigned a, unsigned b) {
    unsigned r; asm("mul.f16x2 %0,%1,%2;" : "=r"(r) : "r"(a), "r"(b)); return r;
}
// w for 2 adjacent j:  exp(lrelu(si+sj)) = max(e^{si}e^{sj}, e^{.2si}e^{.2sj})
__device__ __forceinline__ unsigned wgen2(unsigned Ei2, unsigned Fi2,
                                          unsigned Ej2, unsigned Fj2,
                                          unsigned am) {
    unsigned EE = u_hmul2(Ei2, Ej2);
    unsigned FF = u_hmul2(Fi2, Fj2);
    unsigned m;
    asm("max.f16x2 %0,%1,%2;" : "=r"(m) : "r"(EE), "r"(FF));
    return m & am;
}

// ---------------------------------------------------------------------------
// Kernel A: h = x @ W on fp16 tensor cores (fp32 accum), fused per-node
// scores (exp factors only).  Block = (128 m, one head's 64 n). 256 thr.
// ---------------------------------------------------------------------------
#define GX_STRIDE 136
#define GW_STRIDE 72
#define G_OFF_X 0
#define G_OFF_W 34816
#define G_OFF_A 53248
#define G_SM_TOTAL 53760

__global__ __launch_bounds__(256) void k_gemm(const float* __restrict__ x,
                                              const float* __restrict__ W,
                                              const float* __restrict__ a) {
    extern __shared__ char gsm[];
    __half* Xs = (__half*)(gsm + G_OFF_X);
    __half* Ws = (__half*)(gsm + G_OFF_W);
    float*  Av = (float*)(gsm + G_OFF_A);

    const int tid  = threadIdx.x;
    const int lane = tid & 31;
    const int warp = tid >> 5;
    const int m0 = blockIdx.x * 128;
    const int hd = blockIdx.y;
    const int n0 = hd * 64;

    if (tid < 128) Av[tid] = a[tid];

#pragma unroll
    for (int q = 0; q < 16; q++) {
        int f = tid + q * 256;
        int row = f >> 5;
        int seg = f & 31;
        float4 v = *(const float4*)(x + (size_t)(m0 + row) * 128 + seg * 4);
        __half2 hp[2] = {__floats2half2_rn(v.x, v.y), __floats2half2_rn(v.z, v.w)};
        *(uint2*)(Xs + row * GX_STRIDE + seg * 4) = *(uint2*)hp;
    }
#pragma unroll
    for (int q = 0; q < 8; q++) {
        int f = tid + q * 256;
        int row = f >> 4;
        int seg = f & 15;
        float4 v = *(const float4*)(W + (size_t)row * 256 + n0 + seg * 4);
        __half2 hp[2] = {__floats2half2_rn(v.x, v.y), __floats2half2_rn(v.z, v.w)};
        *(uint2*)(Ws + row * GW_STRIDE + seg * 4) = *(uint2*)hp;
    }
    __syncthreads();

    float acc[8][4];
#pragma unroll
    for (int t = 0; t < 8; t++)
#pragma unroll
        for (int v = 0; v < 4; v++) acc[t][v] = 0.f;

    const int mrow = warp * 16;
#pragma unroll
    for (int k0 = 0; k0 < 128; k0 += 16) {
        unsigned af[4];
        {
            unsigned addr = (unsigned)__cvta_generic_to_shared(
                Xs + (mrow + (lane & 15)) * GX_STRIDE + k0 + ((lane >> 4) << 3));
            asm volatile(
                "ldmatrix.sync.aligned.m8n8.x4.shared.b16 {%0,%1,%2,%3}, [%4];"
                : "=r"(af[0]), "=r"(af[1]), "=r"(af[2]), "=r"(af[3]) : "r"(addr));
        }
        unsigned bf[8][2];
#pragma unroll
        for (int p = 0; p < 4; p++) {
            unsigned addr = (unsigned)__cvta_generic_to_shared(
                Ws + (k0 + (lane & 15)) * GW_STRIDE + p * 16 + ((lane >> 4) << 3));
            asm volatile(
                "ldmatrix.sync.aligned.m8n8.x4.trans.shared.b16 {%0,%1,%2,%3}, [%4];"
                : "=r"(bf[2 * p][0]), "=r"(bf[2 * p][1]),
                  "=r"(bf[2 * p + 1][0]), "=r"(bf[2 * p + 1][1])
                : "r"(addr));
        }
#pragma unroll
        for (int t = 0; t < 8; t++) {
            asm volatile(
                "mma.sync.aligned.m16n8k16.row.col.f32.f16.f16.f32 "
                "{%0,%1,%2,%3}, {%4,%5,%6,%7}, {%8,%9}, {%0,%1,%2,%3};"
                : "+f"(acc[t][0]), "+f"(acc[t][1]), "+f"(acc[t][2]), "+f"(acc[t][3])
                : "r"(af[0]), "r"(af[1]), "r"(af[2]), "r"(af[3]),
                  "r"(bf[t][0]), "r"(bf[t][1]));
        }
    }

    const int r0 = m0 + mrow + (lane >> 2);
    const int r1 = r0 + 8;
    float si0 = 0.f, sj0 = 0.f, si1 = 0.f, sj1 = 0.f;
#pragma unroll
    for (int t = 0; t < 8; t++) {
        int c = t * 8 + (lane & 3) * 2;
        __half2 h0 = __floats2half2_rn(acc[t][0], acc[t][1]);
        __half2 h1 = __floats2half2_rn(acc[t][2], acc[t][3]);
        *(__half2*)(g_h16 + (size_t)r0 * 256 + n0 + c) = h0;
        *(__half2*)(g_h16 + (size_t)r1 * 256 + n0 + c) = h1;
        float a0 = Av[c], a1 = Av[c + 1];
        float b0 = Av[64 + c], b1 = Av[64 + c + 1];
        si0 += acc[t][0] * a0 + acc[t][1] * a1;
        sj0 += acc[t][0] * b0 + acc[t][1] * b1;
        si1 += acc[t][2] * a0 + acc[t][3] * a1;
        sj1 += acc[t][2] * b0 + acc[t][3] * b1;
    }
#pragma unroll
    for (int o = 1; o <= 2; o <<= 1) {
        si0 += __shfl_xor_sync(0xFFFFFFFFu, si0, o);
        sj0 += __shfl_xor_sync(0xFFFFFFFFu, sj0, o);
        si1 += __shfl_xor_sync(0xFFFFFFFFu, si1, o);
        sj1 += __shfl_xor_sync(0xFFFFFFFFu, sj1, o);
    }
    if ((lane & 3) == 0) {
        int o0 = hd * BN + r0;
        int o1 = hd * BN + r1;
        g_Eih[o0] = __float2half_rn(__expf(si0));
        g_Fih[o0] = __float2half_rn(__expf(0.2f * si0));
        g_Ejh[o0] = __float2half_rn(__expf(sj0));
        g_Fjh[o0] = __float2half_rn(__expf(0.2f * sj0));
        g_Eih[o1] = __float2half_rn(__expf(si1));
        g_Fih[o1] = __float2half_rn(__expf(0.2f * si1));
        g_Ejh[o1] = __float2half_rn(__expf(sj1));
        g_Fjh[o1] = __float2half_rn(__expf(0.2f * sj1));
    }
}

// ---------------------------------------------------------------------------
// Kernel C: tensor-core masked-softmax aggregation.
// Block = (b, 64 i-rows, head-pair). grid (32, 8), 256 thr = 8 warps =
// 2 i-slots(m32) x 2 heads x 2 j-halves. 128-j chunks (8 chunks),
// adjacency via DIRECT per-thread LDG.64 at fragment coords (no smem stage),
// EF factors interleaved (Ej2,Fj2) uint2. Ones B-frag denominator.
// ---------------------------------------------------------------------------
#define BS_STRIDE 136                          // halves/row (128 + pad)
#define BS_CH     (128 * BS_STRIDE)            // halves per stage (17408)
#define OFF_BS 0                               // 2*17408*2 = 69632
#define OFF_EF 69632                           // [2][512] uint2 = 8192
#define SM_TOTAL 77824

__global__ __launch_bounds__(256, 2) void k_aggr(const int* __restrict__ adj,
                                                 float* __restrict__ out) {
    extern __shared__ char smem[];
    __half* Bs  = (__half*)(smem + OFF_BS);    // [2][128][BS_STRIDE]
    uint2*  EFp = (uint2*)(smem + OFF_EF);     // [2 heads][512] = (Ej2,Fj2)

    const int tid  = threadIdx.x;
    const int lane = tid & 31;
    const int warp = tid >> 5;
    const int wi   = warp & 1;            // i-slot (32 rows)
    const int hw   = (warp >> 1) & 1;     // head within pair
    const int jh   = warp >> 2;           // j-half: ks in {4jh..4jh+3} of 8
    const int b    = blockIdx.y;
    const int i0   = (blockIdx.x >> 1) * 64;
    const int hp   = blockIdx.x & 1;      // head pair
    const int head = hp * 2 + hw;

    // preload j-side exp factors, interleaved (Ej2,Fj2) pairs
    {
        int h = tid >> 7, idx = tid & 127;
        int o = (hp * 2 + h) * BN + b * NN + idx * 8;
        uint4 e = *(const uint4*)(g_Ejh + o);
        uint4 f = *(const uint4*)(g_Fjh + o);
        uint4* dst = (uint4*)(EFp + h * 512 + idx * 4);
        dst[0] = make_uint4(e.x, f.x, e.y, f.y);
        dst[1] = make_uint4(e.z, f.z, e.w, f.w);
    }

    // per-thread i-side broadcasts: 4 rows = 2 m-tiles x (lo,hi)
    const int hoff = head * BN + b * NN;
    const int rbase = wi * 32 + (lane >> 2);     // local row base
    unsigned Ei2[4], Fi2[4];
#pragma unroll
    for (int r = 0; r < 4; r++) {
        __half2 v;
        v = __half2half2(g_Eih[hoff + i0 + rbase + r * 8]); Ei2[r] = *(unsigned*)&v;
        v = __half2half2(g_Fih[hoff + i0 + rbase + r * 8]); Fi2[r] = *(unsigned*)&v;
    }

    const __half* h16b = g_h16 + (size_t)b * NN * 256 + hp * 128;
    const int jcol = (lane & 3) * 2;
    // direct adjacency row pointers (4 rows of this thread's fragments)
    const int* ar0 = adj + ((size_t)b * NN + i0 + rbase) * NN;
    const int* ar1 = ar0 + (size_t)8 * NN;
    const int* ar2 = ar0 + (size_t)16 * NN;
    const int* ar3 = ar0 + (size_t)24 * NN;
    const uint2* EFh = EFp + hw * 512;
    const unsigned bt8_0 = (lane < 4) ? 0x3C003C00u : 0u;   // ones B-frag

    float acc[2][9][4];
#pragma unroll
    for (int mt = 0; mt < 2; mt++)
#pragma unroll
        for (int t = 0; t < 9; t++)
#pragma unroll
            for (int v = 0; v < 4; v++) acc[mt][t][v] = 0.f;

    // cp.async roles for Bs (256 thr: 128 rows x 256B, 2 thr/row, 128B each)
    const int bs_row = tid >> 1;                 // 0..127
    const int bs_seg = (tid & 1) * 64;           // halves
    const unsigned bs_base = (unsigned)__cvta_generic_to_shared(Bs);

    auto issue_bs = [&](int jc, int s) {
        const __half* src = h16b + (size_t)(jc * 128 + bs_row) * 256 + bs_seg;
        unsigned dst = bs_base + (s * BS_CH + bs_row * BS_STRIDE + bs_seg) * 2;
#pragma unroll
        for (int q = 0; q < 8; q++) cp16(dst + q * 16, src + q * 8);
        cp_commit();
    };

    issue_bs(0, 0);
    issue_bs(1, 1);

    for (int c = 0; c < 8; c++) {
        const int buf = c & 1;
        if (c < 7) asm volatile("cp.async.wait_group 1;");
        else       asm volatile("cp.async.wait_group 0;");
        __syncthreads();                       // Bs(c) visible

        __half* BsC = Bs + buf * BS_CH;
        const int j0 = c * 128;

        // this warp's 4 ks of the 8 (j-split); one B set serves 2 m-tiles
#pragma unroll
        for (int q = 0; q < 4; q++) {
            const int ks = jh * 4 + q;
            const int jl = ks * 16 + jcol;     // local j (even), 0..127
            const int jg = j0 + jl;            // global j

            // direct adjacency loads (8x LDG.64, L2-resident)
            int2 p00 = *(const int2*)(ar0 + jg);
            int2 p08 = *(const int2*)(ar0 + jg + 8);
            int2 p10 = *(const int2*)(ar1 + jg);
            int2 p18 = *(const int2*)(ar1 + jg + 8);
            int2 p20 = *(const int2*)(ar2 + jg);
            int2 p28 = *(const int2*)(ar2 + jg + 8);
            int2 p30 = *(const int2*)(ar3 + jg);
            int2 p38 = *(const int2*)(ar3 + jg + 8);

            uint2 ef0 = EFh[jg >> 1];          // (Ej2, Fj2) at jg
            uint2 ef8 = EFh[(jg >> 1) + 4];    // at jg+8

            // B fragments (shared by both m-tiles)
            const int krow = jl - jcol + (lane & 15);
            unsigned bt[8][2];
#pragma unroll
            for (int p = 0; p < 4; p++) {
                int nb = hw * 64 + p * 16 + ((lane >> 4) << 3);
                unsigned addr = (unsigned)__cvta_generic_to_shared(
                    BsC + krow * BS_STRIDE + nb);
                asm volatile(
                    "ldmatrix.sync.aligned.m8n8.x4.trans.shared.b16 {%0,%1,%2,%3}, [%4];"
                    : "=r"(bt[2 * p][0]), "=r"(bt[2 * p][1]),
                      "=r"(bt[2 * p + 1][0]), "=r"(bt[2 * p + 1][1])
                    : "r"(addr));
            }

#pragma unroll
            for (int mt = 0; mt < 2; mt++) {
                unsigned m_l0, m_l8, m_h0, m_h8;
                if (mt == 0) {
                    m_l0 = __byte_perm((unsigned)(-p00.x), (unsigned)(-p00.y), 0x5410);
                    m_l8 = __byte_perm((unsigned)(-p08.x), (unsigned)(-p08.y), 0x5410);
                    m_h0 = __byte_perm((unsigned)(-p10.x), (unsigned)(-p10.y), 0x5410);
                    m_h8 = __byte_perm((unsigned)(-p18.x), (unsigned)(-p18.y), 0x5410);
                } else {
                    m_l0 = __byte_perm((unsigned)(-p20.x), (unsigned)(-p20.y), 0x5410);
                    m_l8 = __byte_perm((unsigned)(-p28.x), (unsigned)(-p28.y), 0x5410);
                    m_h0 = __byte_perm((unsigned)(-p30.x), (unsigned)(-p30.y), 0x5410);
                    m_h8 = __byte_perm((unsigned)(-p38.x), (unsigned)(-p38.y), 0x5410);
                }

                unsigned a0 = wgen2(Ei2[mt * 2], Fi2[mt * 2], ef0.x, ef0.y, m_l0);
                unsigned a1 = wgen2(Ei2[mt * 2 + 1], Fi2[mt * 2 + 1], ef0.x, ef0.y, m_h0);
                unsigned a2 = wgen2(Ei2[mt * 2], Fi2[mt * 2], ef8.x, ef8.y, m_l8);
                unsigned a3 = wgen2(Ei2[mt * 2 + 1], Fi2[mt * 2 + 1], ef8.x, ef8.y, m_h8);

#pragma unroll
                for (int t = 0; t < 8; t++) {
                    asm volatile(
                        "mma.sync.aligned.m16n8k16.row.col.f32.f16.f16.f32 "
                        "{%0,%1,%2,%3}, {%4,%5,%6,%7}, {%8,%9}, {%0,%1,%2,%3};"
                        : "+f"(acc[mt][t][0]), "+f"(acc[mt][t][1]),
                          "+f"(acc[mt][t][2]), "+f"(acc[mt][t][3])
                        : "r"(a0), "r"(a1), "r"(a2), "r"(a3),
                          "r"(bt[t][0]), "r"(bt[t][1]));
                }
                asm volatile(
                    "mma.sync.aligned.m16n8k16.row.col.f32.f16.f16.f32 "
                    "{%0,%1,%2,%3}, {%4,%5,%6,%7}, {%8,%9}, {%0,%1,%2,%3};"
                    : "+f"(acc[mt][8][0]), "+f"(acc[mt][8][1]),
                      "+f"(acc[mt][8][2]), "+f"(acc[mt][8][3])
                    : "r"(a0), "r"(a1), "r"(a2), "r"(a3),
                      "r"(bt8_0), "r"(bt8_0));
            }
        }

        __syncthreads();                       // compute(c) done everywhere
        if (c < 6) issue_bs(c + 2, buf);       // refill the freed slot
    }

    // ---- combine j-halves: warps 4-7 dump accs (72 floats), warps 0-3 add ----
    float* red = (float*)smem;                 // 128 thr x 72 floats = 36864 B
    __syncthreads();                           // done with Bs region
    if (jh == 1) {
        float* p = red + (tid - 128) * 72;
#pragma unroll
        for (int mt = 0; mt < 2; mt++)
#pragma unroll
            for (int t = 0; t < 9; t++)
                *(float4*)(p + (mt * 9 + t) * 4) = *(float4*)acc[mt][t];
    }
    __syncthreads();
    if (jh == 0) {
        const float* p = red + tid * 72;
#pragma unroll
        for (int mt = 0; mt < 2; mt++)
#pragma unroll
            for (int t = 0; t < 9; t++) {
                float4 v = *(const float4*)(p + (mt * 9 + t) * 4);
                acc[mt][t][0] += v.x; acc[mt][t][1] += v.y;
                acc[mt][t][2] += v.z; acc[mt][t][3] += v.w;
            }

        // epilogue: per m-tile denominators from ones tile, divide, store
#pragma unroll
        for (int mt = 0; mt < 2; mt++) {
            float den_lo = __shfl_sync(0xFFFFFFFFu, acc[mt][8][0], lane & 28);
            float den_hi = __shfl_sync(0xFFFFFFFFu, acc[mt][8][2], lane & 28);
            float inv_lo = 1.0f / den_lo;
            float inv_hi = 1.0f / den_hi;

            const size_t row_lo = (size_t)b * NN + i0 + rbase + mt * 16;
            const size_t row_hi = row_lo + 8;
#pragma unroll
            for (int t = 0; t < 8; t++) {
                int col = head * 64 + t * 8 + (lane & 3) * 2;
                float2 vlo = make_float2(acc[mt][t][0] * inv_lo,
                                         acc[mt][t][1] * inv_lo);
                float2 vhi = make_float2(acc[mt][t][2] * inv_hi,
                                         acc[mt][t][3] * inv_hi);
                *(float2*)(out + row_lo * 256 + col) = vlo;
                *(float2*)(out + row_hi * 256 + col) = vhi;
            }
        }
    }
}

// ---------------------------------------------------------------------------
extern "C" void kernel_launch(void* const* d_in, const int* in_sizes, int n_in,
                              void* d_out, int out_size) {
    const float* x   = (const float*)d_in[0];   // [8,1024,128]
    const int*   adj = (const int*)d_in[1];     // [8,1024,1024]
    const float* W   = (const float*)d_in[2];   // [128,256]
    const float* a   = (const float*)d_in[3];   // [128]
    float* out = (float*)d_out;                 // [8,1024,256]

    cudaFuncSetAttribute(k_gemm, cudaFuncAttributeMaxDynamicSharedMemorySize,
                         G_SM_TOTAL);
    cudaFuncSetAttribute(k_aggr, cudaFuncAttributeMaxDynamicSharedMemorySize,
                         SM_TOTAL);

    k_gemm<<<dim3(BN / 128, NH), 256, G_SM_TOTAL>>>(x, W, a);
    k_aggr<<<dim3(32, BB), 256, SM_TOTAL>>>(adj, out);
}

// round 16
// speedup vs baseline: 1.2011x; 1.2011x over previous
#include <cuda_runtime.h>
#include <cuda_fp16.h>
#include <cuda_bf16.h>

// Problem constants (fixed by reference setup_inputs)
#define BB 8
#define NN 1024
#define BN 8192          // B*N
#define INF 128
#define OUTF 256
#define NH 4
#define DD 64

// Scratch (device globals)
__device__ __half g_h16[BN * OUTF];     // h in fp16 (MMA B operand)
__device__ __half g_Eih[NH * BN];       // e^{s_i}
__device__ __half g_Fih[NH * BN];       // e^{0.2 s_i}
__device__ __half g_Ejh[NH * BN];       // e^{s_j}
__device__ __half g_Fjh[NH * BN];       // e^{0.2 s_j}

// cp.async helpers
__device__ __forceinline__ void cp16(unsigned dst, const void* src) {
    asm volatile("cp.async.cg.shared.global [%0], [%1], 16;" :: "r"(dst), "l"(src));
}
__device__ __forceinline__ void cp_commit() {
    asm volatile("cp.async.commit_group;");
}

// f16x2-as-u32 helpers
__device__ __forceinline__ unsigned u_hmul2(unsigned a, unsigned b) {
    unsigned r; asm("mul.f16x2 %0,%1,%2;" : "=r"(r) : "r"(a), "r"(b)); return r;
}
// w for 2 adjacent j:  exp(lrelu(si+sj)) = max(e^{si}e^{sj}, e^{.2si}e^{.2sj})
__device__ __forceinline__ unsigned wgen2(unsigned Ei2, unsigned Fi2,
                                          unsigned Ej2, unsigned Fj2,
                                          unsigned am) {
    unsigned EE = u_hmul2(Ei2, Ej2);
    unsigned FF = u_hmul2(Fi2, Fj2);
    unsigned m;
    asm("max.f16x2 %0,%1,%2;" : "=r"(m) : "r"(EE), "r"(FF));
    return m & am;
}

// ---------------------------------------------------------------------------
// Kernel A: h = x @ W on fp16 tensor cores (fp32 accum), fused per-node
// scores (exp factors only).  Block = (128 m, one head's 64 n). 256 thr.
// ---------------------------------------------------------------------------
#define GX_STRIDE 136
#define GW_STRIDE 72
#define G_OFF_X 0
#define G_OFF_W 34816
#define G_OFF_A 53248
#define G_SM_TOTAL 53760

__global__ __launch_bounds__(256) void k_gemm(const float* __restrict__ x,
                                              const float* __restrict__ W,
                                              const float* __restrict__ a) {
    extern __shared__ char gsm[];
    __half* Xs = (__half*)(gsm + G_OFF_X);
    __half* Ws = (__half*)(gsm + G_OFF_W);
    float*  Av = (float*)(gsm + G_OFF_A);

    const int tid  = threadIdx.x;
    const int lane = tid & 31;
    const int warp = tid >> 5;
    const int m0 = blockIdx.x * 128;
    const int hd = blockIdx.y;
    const int n0 = hd * 64;

    if (tid < 128) Av[tid] = a[tid];

#pragma unroll
    for (int q = 0; q < 16; q++) {
        int f = tid + q * 256;
        int row = f >> 5;
        int seg = f & 31;
        float4 v = *(const float4*)(x + (size_t)(m0 + row) * 128 + seg * 4);
        __half2 hp[2] = {__floats2half2_rn(v.x, v.y), __floats2half2_rn(v.z, v.w)};
        *(uint2*)(Xs + row * GX_STRIDE + seg * 4) = *(uint2*)hp;
    }
#pragma unroll
    for (int q = 0; q < 8; q++) {
        int f = tid + q * 256;
        int row = f >> 4;
        int seg = f & 15;
        float4 v = *(const float4*)(W + (size_t)row * 256 + n0 + seg * 4);
        __half2 hp[2] = {__floats2half2_rn(v.x, v.y), __floats2half2_rn(v.z, v.w)};
        *(uint2*)(Ws + row * GW_STRIDE + seg * 4) = *(uint2*)hp;
    }
    __syncthreads();

    float acc[8][4];
#pragma unroll
    for (int t = 0; t < 8; t++)
#pragma unroll
        for (int v = 0; v < 4; v++) acc[t][v] = 0.f;

    const int mrow = warp * 16;
#pragma unroll
    for (int k0 = 0; k0 < 128; k0 += 16) {
        unsigned af[4];
        {
            unsigned addr = (unsigned)__cvta_generic_to_shared(
                Xs + (mrow + (lane & 15)) * GX_STRIDE + k0 + ((lane >> 4) << 3));
            asm volatile(
                "ldmatrix.sync.aligned.m8n8.x4.shared.b16 {%0,%1,%2,%3}, [%4];"
                : "=r"(af[0]), "=r"(af[1]), "=r"(af[2]), "=r"(af[3]) : "r"(addr));
        }
        unsigned bf[8][2];
#pragma unroll
        for (int p = 0; p < 4; p++) {
            unsigned addr = (unsigned)__cvta_generic_to_shared(
                Ws + (k0 + (lane & 15)) * GW_STRIDE + p * 16 + ((lane >> 4) << 3));
            asm volatile(
                "ldmatrix.sync.aligned.m8n8.x4.trans.shared.b16 {%0,%1,%2,%3}, [%4];"
                : "=r"(bf[2 * p][0]), "=r"(bf[2 * p][1]),
                  "=r"(bf[2 * p + 1][0]), "=r"(bf[2 * p + 1][1])
                : "r"(addr));
        }
#pragma unroll
        for (int t = 0; t < 8; t++) {
            asm volatile(
                "mma.sync.aligned.m16n8k16.row.col.f32.f16.f16.f32 "
                "{%0,%1,%2,%3}, {%4,%5,%6,%7}, {%8,%9}, {%0,%1,%2,%3};"
                : "+f"(acc[t][0]), "+f"(acc[t][1]), "+f"(acc[t][2]), "+f"(acc[t][3])
                : "r"(af[0]), "r"(af[1]), "r"(af[2]), "r"(af[3]),
                  "r"(bf[t][0]), "r"(bf[t][1]));
        }
    }

    const int r0 = m0 + mrow + (lane >> 2);
    const int r1 = r0 + 8;
    float si0 = 0.f, sj0 = 0.f, si1 = 0.f, sj1 = 0.f;
#pragma unroll
    for (int t = 0; t < 8; t++) {
        int c = t * 8 + (lane & 3) * 2;
        __half2 h0 = __floats2half2_rn(acc[t][0], acc[t][1]);
        __half2 h1 = __floats2half2_rn(acc[t][2], acc[t][3]);
        *(__half2*)(g_h16 + (size_t)r0 * 256 + n0 + c) = h0;
        *(__half2*)(g_h16 + (size_t)r1 * 256 + n0 + c) = h1;
        float a0 = Av[c], a1 = Av[c + 1];
        float b0 = Av[64 + c], b1 = Av[64 + c + 1];
        si0 += acc[t][0] * a0 + acc[t][1] * a1;
        sj0 += acc[t][0] * b0 + acc[t][1] * b1;
        si1 += acc[t][2] * a0 + acc[t][3] * a1;
        sj1 += acc[t][2] * b0 + acc[t][3] * b1;
    }
#pragma unroll
    for (int o = 1; o <= 2; o <<= 1) {
        si0 += __shfl_xor_sync(0xFFFFFFFFu, si0, o);
        sj0 += __shfl_xor_sync(0xFFFFFFFFu, sj0, o);
        si1 += __shfl_xor_sync(0xFFFFFFFFu, si1, o);
        sj1 += __shfl_xor_sync(0xFFFFFFFFu, sj1, o);
    }
    if ((lane & 3) == 0) {
        int o0 = hd * BN + r0;
        int o1 = hd * BN + r1;
        g_Eih[o0] = __float2half_rn(__expf(si0));
        g_Fih[o0] = __float2half_rn(__expf(0.2f * si0));
        g_Ejh[o0] = __float2half_rn(__expf(sj0));
        g_Fjh[o0] = __float2half_rn(__expf(0.2f * sj0));
        g_Eih[o1] = __float2half_rn(__expf(si1));
        g_Fih[o1] = __float2half_rn(__expf(0.2f * si1));
        g_Ejh[o1] = __float2half_rn(__expf(sj1));
        g_Fjh[o1] = __float2half_rn(__expf(0.2f * sj1));
    }
}

// ---------------------------------------------------------------------------
// Kernel C: tensor-core masked-softmax aggregation (R14 winner + EF uint2).
// Block = (b, 64 i-rows, head-pair). grid (32, 8), 256 thr = 8 warps =
// 2 i-slots(m32) x 2 heads x 2 j-halves. m32 per warp: one B-fragment set
// feeds 2 m16 mma batches. j-halves merged via smem epilogue.
// 2-stage cp.async h16 ring; adjacency staged as u16 masks (LDG->PRMT->STS).
// EF factors interleaved (Ej2,Fj2) uint2: 2x LDS.64 per ks instead of 4x LDS.32.
// ---------------------------------------------------------------------------
#define BS_STRIDE 136                          // halves/row (128 + pad)
#define BS_CH     (64 * BS_STRIDE)             // halves per stage (8704)
#define AM_STRIDE 72                           // u16/row (64 + pad)
#define AM_CH     (64 * AM_STRIDE)             // u16 per stage (4608)
#define OFF_BS 0                               // 2*8704*2  = 34816
#define OFF_AM 34816                           // 2*4608*2  = 18432
#define OFF_EF 53248                           // [2][512] uint2 = 8192
#define SM_TOTAL 61440

__global__ __launch_bounds__(256, 2) void k_aggr(const int* __restrict__ adj,
                                                 float* __restrict__ out) {
    extern __shared__ char smem[];
    __half*         Bs  = (__half*)(smem + OFF_BS);            // [2][64][BS_STRIDE]
    unsigned short* AM  = (unsigned short*)(smem + OFF_AM);    // [2][64][AM_STRIDE]
    uint2*          EFp = (uint2*)(smem + OFF_EF);             // [2 heads][512]

    const int tid  = threadIdx.x;
    const int lane = tid & 31;
    const int warp = tid >> 5;
    const int wi   = warp & 1;            // i-slot (32 rows)
    const int hw   = (warp >> 1) & 1;     // head within pair
    const int jh   = warp >> 2;           // j-half: ks in {2jh, 2jh+1}
    const int b    = blockIdx.y;
    const int i0   = (blockIdx.x >> 1) * 64;
    const int hp   = blockIdx.x & 1;      // head pair
    const int head = hp * 2 + hw;

    // preload j-side exp factors, interleaved (Ej2,Fj2) pairs
    {
        int h = tid >> 7, idx = tid & 127;
        int o = (hp * 2 + h) * BN + b * NN + idx * 8;
        uint4 e = *(const uint4*)(g_Ejh + o);
        uint4 f = *(const uint4*)(g_Fjh + o);
        uint4* dst = (uint4*)(EFp + h * 512 + idx * 4);
        dst[0] = make_uint4(e.x, f.x, e.y, f.y);
        dst[1] = make_uint4(e.z, f.z, e.w, f.w);
    }

    // per-thread i-side broadcasts: 4 rows = 2 m-tiles x (lo,hi)
    const int hoff = head * BN + b * NN;
    const int rbase = wi * 32 + (lane >> 2);     // local row base
    unsigned Ei2[4], Fi2[4];
#pragma unroll
    for (int r = 0; r < 4; r++) {
        __half2 v;
        v = __half2half2(g_Eih[hoff + i0 + rbase + r * 8]); Ei2[r] = *(unsigned*)&v;
        v = __half2half2(g_Fih[hoff + i0 + rbase + r * 8]); Fi2[r] = *(unsigned*)&v;
    }

    const __half* h16b = g_h16 + (size_t)b * NN * 256 + hp * 128;
    const int*    adjb = adj + (size_t)b * NN * NN;
    const int jcol = (lane & 3) * 2;
    const uint2* EFh = EFp + hw * 512;
    const unsigned bt8_0 = (lane < 4) ? 0x3C003C00u : 0u;   // ones B-frag

    float acc[2][9][4];
#pragma unroll
    for (int mt = 0; mt < 2; mt++)
#pragma unroll
        for (int t = 0; t < 9; t++)
#pragma unroll
            for (int v = 0; v < 4; v++) acc[mt][t][v] = 0.f;

    // cp.async roles for Bs (256 thr, 64B each)
    const int bs_row = tid >> 2;                 // 0..63
    const int bs_seg = (tid & 3) * 32;           // halves
    const unsigned bs_base = (unsigned)__cvta_generic_to_shared(Bs);

    // adjacency staging roles: 16 ints per thread (one quarter row)
    const int st_row = tid >> 2;                 // 0..63
    const int st_seg = (tid & 3) * 16;           // ints / u16 units
    const int* st_src = adjb + (size_t)(i0 + st_row) * NN + st_seg;

    auto issue_bs = [&](int jc, int s) {
        const __half* src = h16b + (size_t)(jc * 64 + bs_row) * 256 + bs_seg;
        unsigned dst = bs_base + (s * BS_CH + bs_row * BS_STRIDE + bs_seg) * 2;
#pragma unroll
        for (int q = 0; q < 4; q++) cp16(dst + q * 16, src + q * 8);
        cp_commit();
    };

    // prolog: adjacency ints for chunk 0 into regs; Bs chunks 0,1 in flight
    int4 pre[4];
#pragma unroll
    for (int q = 0; q < 4; q++) pre[q] = *(const int4*)(st_src + q * 4);
    issue_bs(0, 0);
    issue_bs(1, 1);

    for (int c = 0; c < 16; c++) {
        const int buf = c & 1;

        // convert + store adjacency masks for chunk c (regs -> smem u16 masks)
        {
            unsigned short* amrow = AM + buf * AM_CH + st_row * AM_STRIDE + st_seg;
            uint4 w0, w1;
            w0.x = __byte_perm((unsigned)(-pre[0].x), (unsigned)(-pre[0].y), 0x5410);
            w0.y = __byte_perm((unsigned)(-pre[0].z), (unsigned)(-pre[0].w), 0x5410);
            w0.z = __byte_perm((unsigned)(-pre[1].x), (unsigned)(-pre[1].y), 0x5410);
            w0.w = __byte_perm((unsigned)(-pre[1].z), (unsigned)(-pre[1].w), 0x5410);
            w1.x = __byte_perm((unsigned)(-pre[2].x), (unsigned)(-pre[2].y), 0x5410);
            w1.y = __byte_perm((unsigned)(-pre[2].z), (unsigned)(-pre[2].w), 0x5410);
            w1.z = __byte_perm((unsigned)(-pre[3].x), (unsigned)(-pre[3].y), 0x5410);
            w1.w = __byte_perm((unsigned)(-pre[3].z), (unsigned)(-pre[3].w), 0x5410);
            *(uint4*)(amrow)     = w0;
            *(uint4*)(amrow + 8) = w1;
        }
        // prefetch adjacency ints for chunk c+1
        if (c < 15) {
            const int* p = st_src + (c + 1) * 64;
#pragma unroll
            for (int q = 0; q < 4; q++) pre[q] = *(const int4*)(p + q * 4);
        }

        if (c < 15) asm volatile("cp.async.wait_group 1;");
        else        asm volatile("cp.async.wait_group 0;");
        __syncthreads();                       // Bs(c) + AM(c) visible

        __half* BsC = Bs + buf * BS_CH;
        const unsigned short* amC = AM + buf * AM_CH;
        const int j0 = c * 64;

        // this warp's 2 ks of the 4 (j-split); one B set serves 2 m-tiles
#pragma unroll
        for (int q = 0; q < 2; q++) {
            const int ks = jh * 2 + q;
            const int jl = ks * 16 + jcol;     // local j (even)
            const int jg = j0 + jl;
            uint2 ef0 = EFh[jg >> 1];          // (Ej2, Fj2) at jg
            uint2 ef8 = EFh[(jg >> 1) + 4];    // at jg+8

            const int krow = ks * 16 + (lane & 15);
            unsigned bt[8][2];
#pragma unroll
            for (int p = 0; p < 4; p++) {
                int nb = hw * 64 + p * 16 + ((lane >> 4) << 3);
                unsigned addr = (unsigned)__cvta_generic_to_shared(
                    BsC + krow * BS_STRIDE + nb);
                asm volatile(
                    "ldmatrix.sync.aligned.m8n8.x4.trans.shared.b16 {%0,%1,%2,%3}, [%4];"
                    : "=r"(bt[2 * p][0]), "=r"(bt[2 * p][1]),
                      "=r"(bt[2 * p + 1][0]), "=r"(bt[2 * p + 1][1])
                    : "r"(addr));
            }

#pragma unroll
            for (int mt = 0; mt < 2; mt++) {
                const int rlo = rbase + mt * 16;
                const int rhi = rlo + 8;
                unsigned am_lo0 = *(const unsigned*)(amC + rlo * AM_STRIDE + jl);
                unsigned am_lo8 = *(const unsigned*)(amC + rlo * AM_STRIDE + jl + 8);
                unsigned am_hi0 = *(const unsigned*)(amC + rhi * AM_STRIDE + jl);
                unsigned am_hi8 = *(const unsigned*)(amC + rhi * AM_STRIDE + jl + 8);

                unsigned a0 = wgen2(Ei2[mt * 2], Fi2[mt * 2], ef0.x, ef0.y, am_lo0);
                unsigned a1 = wgen2(Ei2[mt * 2 + 1], Fi2[mt * 2 + 1], ef0.x, ef0.y, am_hi0);
                unsigned a2 = wgen2(Ei2[mt * 2], Fi2[mt * 2], ef8.x, ef8.y, am_lo8);
                unsigned a3 = wgen2(Ei2[mt * 2 + 1], Fi2[mt * 2 + 1], ef8.x, ef8.y, am_hi8);

#pragma unroll
                for (int t = 0; t < 8; t++) {
                    asm volatile(
                        "mma.sync.aligned.m16n8k16.row.col.f32.f16.f16.f32 "
                        "{%0,%1,%2,%3}, {%4,%5,%6,%7}, {%8,%9}, {%0,%1,%2,%3};"
                        : "+f"(acc[mt][t][0]), "+f"(acc[mt][t][1]),
                          "+f"(acc[mt][t][2]), "+f"(acc[mt][t][3])
                        : "r"(a0), "r"(a1), "r"(a2), "r"(a3),
                          "r"(bt[t][0]), "r"(bt[t][1]));
                }
                asm volatile(
                    "mma.sync.aligned.m16n8k16.row.col.f32.f16.f16.f32 "
                    "{%0,%1,%2,%3}, {%4,%5,%6,%7}, {%8,%9}, {%0,%1,%2,%3};"
                    : "+f"(acc[mt][8][0]), "+f"(acc[mt][8][1]),
                      "+f"(acc[mt][8][2]), "+f"(acc[mt][8][3])
                    : "r"(a0), "r"(a1), "r"(a2), "r"(a3),
                      "r"(bt8_0), "r"(bt8_0));
            }
        }

        __syncthreads();                       // compute(c) done everywhere
        if (c < 14) issue_bs(c + 2, buf);      // refill the slot just freed
    }

    // ---- combine j-halves: warps 4-7 dump accs (72 floats), warps 0-3 add ----
    float* red = (float*)smem;                 // 128 thr x 72 floats = 36864 B
    __syncthreads();                           // done with Bs/AM regions
    if (jh == 1) {
        float* p = red + (tid - 128) * 72;
#pragma unroll
        for (int mt = 0; mt < 2; mt++)
#pragma unroll
            for (int t = 0; t < 9; t++)
                *(float4*)(p + (mt * 9 + t) * 4) = *(float4*)acc[mt][t];
    }
    __syncthreads();
    if (jh == 0) {
        const float* p = red + tid * 72;
#pragma unroll
        for (int mt = 0; mt < 2; mt++)
#pragma unroll
            for (int t = 0; t < 9; t++) {
                float4 v = *(const float4*)(p + (mt * 9 + t) * 4);
                acc[mt][t][0] += v.x; acc[mt][t][1] += v.y;
                acc[mt][t][2] += v.z; acc[mt][t][3] += v.w;
            }

        // epilogue: per m-tile denominators from ones tile, divide, store
#pragma unroll
        for (int mt = 0; mt < 2; mt++) {
            float den_lo = __shfl_sync(0xFFFFFFFFu, acc[mt][8][0], lane & 28);
            float den_hi = __shfl_sync(0xFFFFFFFFu, acc[mt][8][2], lane & 28);
            float inv_lo = 1.0f / den_lo;
            float inv_hi = 1.0f / den_hi;

            const size_t row_lo = (size_t)b * NN + i0 + rbase + mt * 16;
            const size_t row_hi = row_lo + 8;
#pragma unroll
            for (int t = 0; t < 8; t++) {
                int col = head * 64 + t * 8 + (lane & 3) * 2;
                float2 vlo = make_float2(acc[mt][t][0] * inv_lo,
                                         acc[mt][t][1] * inv_lo);
                float2 vhi = make_float2(acc[mt][t][2] * inv_hi,
                                         acc[mt][t][3] * inv_hi);
                *(float2*)(out + row_lo * 256 + col) = vlo;
                *(float2*)(out + row_hi * 256 + col) = vhi;
            }
        }
    }
}

// ---------------------------------------------------------------------------
extern "C" void kernel_launch(void* const* d_in, const int* in_sizes, int n_in,
                              void* d_out, int out_size) {
    const float* x   = (const float*)d_in[0];   // [8,1024,128]
    const int*   adj = (const int*)d_in[1];     // [8,1024,1024]
    const float* W   = (const float*)d_in[2];   // [128,256]
    const float* a   = (const float*)d_in[3];   // [128]
    float* out = (float*)d_out;                 // [8,1024,256]

    cudaFuncSetAttribute(k_gemm, cudaFuncAttributeMaxDynamicSharedMemorySize,
                         G_SM_TOTAL);
    cudaFuncSetAttribute(k_aggr, cudaFuncAttributeMaxDynamicSharedMemorySize,
                         SM_TOTAL);

    k_gemm<<<dim3(BN / 128, NH), 256, G_SM_TOTAL>>>(x, W, a);
    k_aggr<<<dim3(32, BB), 256, SM_TOTAL>>>(adj, out);
}

// round 17
// speedup vs baseline: 1.2718x; 1.0589x over previous
#include <cuda_runtime.h>
#include <cuda_fp16.h>
#include <cuda_bf16.h>

// Problem constants (fixed by reference setup_inputs)
#define BB 8
#define NN 1024
#define BN 8192          // B*N
#define INF 128
#define OUTF 256
#define NH 4
#define DD 64

// Scratch (device globals)
__device__ __half g_h16[BN * OUTF];     // h in fp16 (MMA B operand)
__device__ __half g_Eih[NH * BN];       // e^{s_i}
__device__ __half g_Fih[NH * BN];       // e^{0.2 s_i}
__device__ __half g_Ejh[NH * BN];       // e^{s_j}
__device__ __half g_Fjh[NH * BN];       // e^{0.2 s_j}

// cp.async helpers
__device__ __forceinline__ void cp16(unsigned dst, const void* src) {
    asm volatile("cp.async.cg.shared.global [%0], [%1], 16;" :: "r"(dst), "l"(src));
}
__device__ __forceinline__ void cp_commit() {
    asm volatile("cp.async.commit_group;");
}

// f16x2-as-u32 helpers
__device__ __forceinline__ unsigned u_hmul2(unsigned a, unsigned b) {
    unsigned r; asm("mul.f16x2 %0,%1,%2;" : "=r"(r) : "r"(a), "r"(b)); return r;
}
// w for 2 adjacent j:  exp(lrelu(si+sj)) = max(e^{si}e^{sj}, e^{.2si}e^{.2sj})
__device__ __forceinline__ unsigned wgen2(unsigned Ei2, unsigned Fi2,
                                          unsigned Ej2, unsigned Fj2,
                                          unsigned am) {
    unsigned EE = u_hmul2(Ei2, Ej2);
    unsigned FF = u_hmul2(Fi2, Fj2);
    unsigned m;
    asm("max.f16x2 %0,%1,%2;" : "=r"(m) : "r"(EE), "r"(FF));
    return m & am;
}

// ---------------------------------------------------------------------------
// Kernel A: h = x @ W on fp16 tensor cores (fp32 accum), fused per-node
// scores (exp factors only).  Block = (128 m, one head's 64 n). 256 thr.
// ---------------------------------------------------------------------------
#define GX_STRIDE 136
#define GW_STRIDE 72
#define G_OFF_X 0
#define G_OFF_W 34816
#define G_OFF_A 53248
#define G_SM_TOTAL 53760

__global__ __launch_bounds__(256) void k_gemm(const float* __restrict__ x,
                                              const float* __restrict__ W,
                                              const float* __restrict__ a) {
    extern __shared__ char gsm[];
    __half* Xs = (__half*)(gsm + G_OFF_X);
    __half* Ws = (__half*)(gsm + G_OFF_W);
    float*  Av = (float*)(gsm + G_OFF_A);

    const int tid  = threadIdx.x;
    const int lane = tid & 31;
    const int warp = tid >> 5;
    const int m0 = blockIdx.x * 128;
    const int hd = blockIdx.y;
    const int n0 = hd * 64;

    if (tid < 128) Av[tid] = a[tid];

#pragma unroll
    for (int q = 0; q < 16; q++) {
        int f = tid + q * 256;
        int row = f >> 5;
        int seg = f & 31;
        float4 v = *(const float4*)(x + (size_t)(m0 + row) * 128 + seg * 4);
        __half2 hp[2] = {__floats2half2_rn(v.x, v.y), __floats2half2_rn(v.z, v.w)};
        *(uint2*)(Xs + row * GX_STRIDE + seg * 4) = *(uint2*)hp;
    }
#pragma unroll
    for (int q = 0; q < 8; q++) {
        int f = tid + q * 256;
        int row = f >> 4;
        int seg = f & 15;
        float4 v = *(const float4*)(W + (size_t)row * 256 + n0 + seg * 4);
        __half2 hp[2] = {__floats2half2_rn(v.x, v.y), __floats2half2_rn(v.z, v.w)};
        *(uint2*)(Ws + row * GW_STRIDE + seg * 4) = *(uint2*)hp;
    }
    __syncthreads();

    float acc[8][4];
#pragma unroll
    for (int t = 0; t < 8; t++)
#pragma unroll
        for (int v = 0; v < 4; v++) acc[t][v] = 0.f;

    const int mrow = warp * 16;
#pragma unroll
    for (int k0 = 0; k0 < 128; k0 += 16) {
        unsigned af[4];
        {
            unsigned addr = (unsigned)__cvta_generic_to_shared(
                Xs + (mrow + (lane & 15)) * GX_STRIDE + k0 + ((lane >> 4) << 3));
            asm volatile(
                "ldmatrix.sync.aligned.m8n8.x4.shared.b16 {%0,%1,%2,%3}, [%4];"
                : "=r"(af[0]), "=r"(af[1]), "=r"(af[2]), "=r"(af[3]) : "r"(addr));
        }
        unsigned bf[8][2];
#pragma unroll
        for (int p = 0; p < 4; p++) {
            unsigned addr = (unsigned)__cvta_generic_to_shared(
                Ws + (k0 + (lane & 15)) * GW_STRIDE + p * 16 + ((lane >> 4) << 3));
            asm volatile(
                "ldmatrix.sync.aligned.m8n8.x4.trans.shared.b16 {%0,%1,%2,%3}, [%4];"
                : "=r"(bf[2 * p][0]), "=r"(bf[2 * p][1]),
                  "=r"(bf[2 * p + 1][0]), "=r"(bf[2 * p + 1][1])
                : "r"(addr));
        }
#pragma unroll
        for (int t = 0; t < 8; t++) {
            asm volatile(
                "mma.sync.aligned.m16n8k16.row.col.f32.f16.f16.f32 "
                "{%0,%1,%2,%3}, {%4,%5,%6,%7}, {%8,%9}, {%0,%1,%2,%3};"
                : "+f"(acc[t][0]), "+f"(acc[t][1]), "+f"(acc[t][2]), "+f"(acc[t][3])
                : "r"(af[0]), "r"(af[1]), "r"(af[2]), "r"(af[3]),
                  "r"(bf[t][0]), "r"(bf[t][1]));
        }
    }

    const int r0 = m0 + mrow + (lane >> 2);
    const int r1 = r0 + 8;
    float si0 = 0.f, sj0 = 0.f, si1 = 0.f, sj1 = 0.f;
#pragma unroll
    for (int t = 0; t < 8; t++) {
        int c = t * 8 + (lane & 3) * 2;
        __half2 h0 = __floats2half2_rn(acc[t][0], acc[t][1]);
        __half2 h1 = __floats2half2_rn(acc[t][2], acc[t][3]);
        *(__half2*)(g_h16 + (size_t)r0 * 256 + n0 + c) = h0;
        *(__half2*)(g_h16 + (size_t)r1 * 256 + n0 + c) = h1;
        float a0 = Av[c], a1 = Av[c + 1];
        float b0 = Av[64 + c], b1 = Av[64 + c + 1];
        si0 += acc[t][0] * a0 + acc[t][1] * a1;
        sj0 += acc[t][0] * b0 + acc[t][1] * b1;
        si1 += acc[t][2] * a0 + acc[t][3] * a1;
        sj1 += acc[t][2] * b0 + acc[t][3] * b1;
    }
#pragma unroll
    for (int o = 1; o <= 2; o <<= 1) {
        si0 += __shfl_xor_sync(0xFFFFFFFFu, si0, o);
        sj0 += __shfl_xor_sync(0xFFFFFFFFu, sj0, o);
        si1 += __shfl_xor_sync(0xFFFFFFFFu, si1, o);
        sj1 += __shfl_xor_sync(0xFFFFFFFFu, sj1, o);
    }
    if ((lane & 3) == 0) {
        int o0 = hd * BN + r0;
        int o1 = hd * BN + r1;
        g_Eih[o0] = __float2half_rn(__expf(si0));
        g_Fih[o0] = __float2half_rn(__expf(0.2f * si0));
        g_Ejh[o0] = __float2half_rn(__expf(sj0));
        g_Fjh[o0] = __float2half_rn(__expf(0.2f * sj0));
        g_Eih[o1] = __float2half_rn(__expf(si1));
        g_Fih[o1] = __float2half_rn(__expf(0.2f * si1));
        g_Ejh[o1] = __float2half_rn(__expf(sj1));
        g_Fjh[o1] = __float2half_rn(__expf(0.2f * sj1));
    }
}

// ---------------------------------------------------------------------------
// Kernel C: tensor-core masked-softmax aggregation (R16 winner + 3-slot
// rings, ONE __syncthreads per chunk).
// Block = (b, 64 i-rows, head-pair). grid (32, 8), 256 thr = 8 warps =
// 2 i-slots(m32) x 2 heads x 2 j-halves. m32 per warp: one B-fragment set
// feeds 2 m16 mma batches. j-halves merged via smem epilogue.
// 3-slot cp.async Bs ring + 3-slot AM ring (LDG->PRMT->STS staged masks).
// EF factors interleaved (Ej2,Fj2) uint2.
// ---------------------------------------------------------------------------
#define BS_STRIDE 136                          // halves/row (128 + pad)
#define BS_CH     (64 * BS_STRIDE)             // halves per slot (8704)
#define AM_STRIDE 72                           // u16/row (64 + pad)
#define AM_CH     (64 * AM_STRIDE)             // u16 per slot (4608)
#define OFF_BS 0                               // 3*8704*2  = 52224
#define OFF_AM 52224                           // 3*4608*2  = 27648
#define OFF_EF 79872                           // [2][512] uint2 = 8192
#define SM_TOTAL 88064

__global__ __launch_bounds__(256, 2) void k_aggr(const int* __restrict__ adj,
                                                 float* __restrict__ out) {
    extern __shared__ char smem[];
    __half*         Bs  = (__half*)(smem + OFF_BS);            // [3][64][BS_STRIDE]
    unsigned short* AM  = (unsigned short*)(smem + OFF_AM);    // [3][64][AM_STRIDE]
    uint2*          EFp = (uint2*)(smem + OFF_EF);             // [2 heads][512]

    const int tid  = threadIdx.x;
    const int lane = tid & 31;
    const int warp = tid >> 5;
    const int wi   = warp & 1;            // i-slot (32 rows)
    const int hw   = (warp >> 1) & 1;     // head within pair
    const int jh   = warp >> 2;           // j-half: ks in {2jh, 2jh+1}
    const int b    = blockIdx.y;
    const int i0   = (blockIdx.x >> 1) * 64;
    const int hp   = blockIdx.x & 1;      // head pair
    const int head = hp * 2 + hw;

    // preload j-side exp factors, interleaved (Ej2,Fj2) pairs
    {
        int h = tid >> 7, idx = tid & 127;
        int o = (hp * 2 + h) * BN + b * NN + idx * 8;
        uint4 e = *(const uint4*)(g_Ejh + o);
        uint4 f = *(const uint4*)(g_Fjh + o);
        uint4* dst = (uint4*)(EFp + h * 512 + idx * 4);
        dst[0] = make_uint4(e.x, f.x, e.y, f.y);
        dst[1] = make_uint4(e.z, f.z, e.w, f.w);
    }

    // per-thread i-side broadcasts: 4 rows = 2 m-tiles x (lo,hi)
    const int hoff = head * BN + b * NN;
    const int rbase = wi * 32 + (lane >> 2);     // local row base
    unsigned Ei2[4], Fi2[4];
#pragma unroll
    for (int r = 0; r < 4; r++) {
        __half2 v;
        v = __half2half2(g_Eih[hoff + i0 + rbase + r * 8]); Ei2[r] = *(unsigned*)&v;
        v = __half2half2(g_Fih[hoff + i0 + rbase + r * 8]); Fi2[r] = *(unsigned*)&v;
    }

    const __half* h16b = g_h16 + (size_t)b * NN * 256 + hp * 128;
    const int*    adjb = adj + (size_t)b * NN * NN;
    const int jcol = (lane & 3) * 2;
    const uint2* EFh = EFp + hw * 512;
    const unsigned bt8_0 = (lane < 4) ? 0x3C003C00u : 0u;   // ones B-frag

    float acc[2][9][4];
#pragma unroll
    for (int mt = 0; mt < 2; mt++)
#pragma unroll
        for (int t = 0; t < 9; t++)
#pragma unroll
            for (int v = 0; v < 4; v++) acc[mt][t][v] = 0.f;

    // cp.async roles for Bs (256 thr, 64B each)
    const int bs_row = tid >> 2;                 // 0..63
    const int bs_seg = (tid & 3) * 32;           // halves
    const unsigned bs_base = (unsigned)__cvta_generic_to_shared(Bs);

    // adjacency staging roles: 16 ints per thread (one quarter row)
    const int st_row = tid >> 2;                 // 0..63
    const int st_seg = (tid & 3) * 16;           // ints / u16 units
    const int* st_src = adjb + (size_t)(i0 + st_row) * NN + st_seg;

    auto issue_bs = [&](int jc, int s) {
        const __half* src = h16b + (size_t)(jc * 64 + bs_row) * 256 + bs_seg;
        unsigned dst = bs_base + (s * BS_CH + bs_row * BS_STRIDE + bs_seg) * 2;
#pragma unroll
        for (int q = 0; q < 4; q++) cp16(dst + q * 16, src + q * 8);
        cp_commit();
    };

    // prolog: adjacency ints for chunk 0 in regs; Bs chunks 0,1 in flight
    int4 pre[4];
#pragma unroll
    for (int q = 0; q < 4; q++) pre[q] = *(const int4*)(st_src + q * 4);
    issue_bs(0, 0);
    issue_bs(1, 1);

    int slot = 0;                                // = c % 3
    for (int c = 0; c < 16; c++) {
        // STS AM(c) into slot (readers of this slot were compute(c-3),
        // complete before any warp passed sync(c-1))
        {
            unsigned short* amrow = AM + slot * AM_CH + st_row * AM_STRIDE + st_seg;
            uint4 w0, w1;
            w0.x = __byte_perm((unsigned)(-pre[0].x), (unsigned)(-pre[0].y), 0x5410);
            w0.y = __byte_perm((unsigned)(-pre[0].z), (unsigned)(-pre[0].w), 0x5410);
            w0.z = __byte_perm((unsigned)(-pre[1].x), (unsigned)(-pre[1].y), 0x5410);
            w0.w = __byte_perm((unsigned)(-pre[1].z), (unsigned)(-pre[1].w), 0x5410);
            w1.x = __byte_perm((unsigned)(-pre[2].x), (unsigned)(-pre[2].y), 0x5410);
            w1.y = __byte_perm((unsigned)(-pre[2].z), (unsigned)(-pre[2].w), 0x5410);
            w1.z = __byte_perm((unsigned)(-pre[3].x), (unsigned)(-pre[3].y), 0x5410);
            w1.w = __byte_perm((unsigned)(-pre[3].z), (unsigned)(-pre[3].w), 0x5410);
            *(uint4*)(amrow)     = w0;
            *(uint4*)(amrow + 8) = w1;
        }
        // prefetch adjacency ints for chunk c+1
        if (c < 15) {
            const int* p = st_src + (c + 1) * 64;
#pragma unroll
            for (int q = 0; q < 4; q++) pre[q] = *(const int4*)(p + q * 4);
        }

        if (c < 15) asm volatile("cp.async.wait_group 1;");
        else        asm volatile("cp.async.wait_group 0;");
        __syncthreads();                       // ONE barrier: Bs(c)+AM(c) visible;
                                               // compute(c-1) done everywhere

        if (c + 2 < 16) {                      // refill slot (c+2)%3 = (c-1)%3
            int ns = slot + 2; if (ns >= 3) ns -= 3;
            issue_bs(c + 2, ns);
        }

        __half* BsC = Bs + slot * BS_CH;
        const unsigned short* amC = AM + slot * AM_CH;
        const int j0 = c * 64;

        // this warp's 2 ks of the 4 (j-split); one B set serves 2 m-tiles
#pragma unroll
        for (int q = 0; q < 2; q++) {
            const int ks = jh * 2 + q;
            const int jl = ks * 16 + jcol;     // local j (even)
            const int jg = j0 + jl;
            uint2 ef0 = EFh[jg >> 1];          // (Ej2, Fj2) at jg
            uint2 ef8 = EFh[(jg >> 1) + 4];    // at jg+8

            const int krow = ks * 16 + (lane & 15);
            unsigned bt[8][2];
#pragma unroll
            for (int p = 0; p < 4; p++) {
                int nb = hw * 64 + p * 16 + ((lane >> 4) << 3);
                unsigned addr = (unsigned)__cvta_generic_to_shared(
                    BsC + krow * BS_STRIDE + nb);
                asm volatile(
                    "ldmatrix.sync.aligned.m8n8.x4.trans.shared.b16 {%0,%1,%2,%3}, [%4];"
                    : "=r"(bt[2 * p][0]), "=r"(bt[2 * p][1]),
                      "=r"(bt[2 * p + 1][0]), "=r"(bt[2 * p + 1][1])
                    : "r"(addr));
            }

#pragma unroll
            for (int mt = 0; mt < 2; mt++) {
                const int rlo = rbase + mt * 16;
                const int rhi = rlo + 8;
                unsigned am_lo0 = *(const unsigned*)(amC + rlo * AM_STRIDE + jl);
                unsigned am_lo8 = *(const unsigned*)(amC + rlo * AM_STRIDE + jl + 8);
                unsigned am_hi0 = *(const unsigned*)(amC + rhi * AM_STRIDE + jl);
                unsigned am_hi8 = *(const unsigned*)(amC + rhi * AM_STRIDE + jl + 8);

                unsigned a0 = wgen2(Ei2[mt * 2], Fi2[mt * 2], ef0.x, ef0.y, am_lo0);
                unsigned a1 = wgen2(Ei2[mt * 2 + 1], Fi2[mt * 2 + 1], ef0.x, ef0.y, am_hi0);
                unsigned a2 = wgen2(Ei2[mt * 2], Fi2[mt * 2], ef8.x, ef8.y, am_lo8);
                unsigned a3 = wgen2(Ei2[mt * 2 + 1], Fi2[mt * 2 + 1], ef8.x, ef8.y, am_hi8);

#pragma unroll
                for (int t = 0; t < 8; t++) {
                    asm volatile(
                        "mma.sync.aligned.m16n8k16.row.col.f32.f16.f16.f32 "
                        "{%0,%1,%2,%3}, {%4,%5,%6,%7}, {%8,%9}, {%0,%1,%2,%3};"
                        : "+f"(acc[mt][t][0]), "+f"(acc[mt][t][1]),
                          "+f"(acc[mt][t][2]), "+f"(acc[mt][t][3])
                        : "r"(a0), "r"(a1), "r"(a2), "r"(a3),
                          "r"(bt[t][0]), "r"(bt[t][1]));
                }
                asm volatile(
                    "mma.sync.aligned.m16n8k16.row.col.f32.f16.f16.f32 "
                    "{%0,%1,%2,%3}, {%4,%5,%6,%7}, {%8,%9}, {%0,%1,%2,%3};"
                    : "+f"(acc[mt][8][0]), "+f"(acc[mt][8][1]),
                      "+f"(acc[mt][8][2]), "+f"(acc[mt][8][3])
                    : "r"(a0), "r"(a1), "r"(a2), "r"(a3),
                      "r"(bt8_0), "r"(bt8_0));
            }
        }

        slot++; if (slot >= 3) slot = 0;
    }

    // ---- combine j-halves: warps 4-7 dump accs (72 floats), warps 0-3 add ----
    float* red = (float*)smem;                 // 128 thr x 72 floats = 36864 B
    __syncthreads();                           // done with Bs/AM regions
    if (jh == 1) {
        float* p = red + (tid - 128) * 72;
#pragma unroll
        for (int mt = 0; mt < 2; mt++)
#pragma unroll
            for (int t = 0; t < 9; t++)
                *(float4*)(p + (mt * 9 + t) * 4) = *(float4*)acc[mt][t];
    }
    __syncthreads();
    if (jh == 0) {
        const float* p = red + tid * 72;
#pragma unroll
        for (int mt = 0; mt < 2; mt++)
#pragma unroll
            for (int t = 0; t < 9; t++) {
                float4 v = *(const float4*)(p + (mt * 9 + t) * 4);
                acc[mt][t][0] += v.x; acc[mt][t][1] += v.y;
                acc[mt][t][2] += v.z; acc[mt][t][3] += v.w;
            }

        // epilogue: per m-tile denominators from ones tile, divide, store
#pragma unroll
        for (int mt = 0; mt < 2; mt++) {
            float den_lo = __shfl_sync(0xFFFFFFFFu, acc[mt][8][0], lane & 28);
            float den_hi = __shfl_sync(0xFFFFFFFFu, acc[mt][8][2], lane & 28);
            float inv_lo = 1.0f / den_lo;
            float inv_hi = 1.0f / den_hi;

            const size_t row_lo = (size_t)b * NN + i0 + rbase + mt * 16;
            const size_t row_hi = row_lo + 8;
#pragma unroll
            for (int t = 0; t < 8; t++) {
                int col = head * 64 + t * 8 + (lane & 3) * 2;
                float2 vlo = make_float2(acc[mt][t][0] * inv_lo,
                                         acc[mt][t][1] * inv_lo);
                float2 vhi = make_float2(acc[mt][t][2] * inv_hi,
                                         acc[mt][t][3] * inv_hi);
                *(float2*)(out + row_lo * 256 + col) = vlo;
                *(float2*)(out + row_hi * 256 + col) = vhi;
            }
        }
    }
}

// ---------------------------------------------------------------------------
extern "C" void kernel_launch(void* const* d_in, const int* in_sizes, int n_in,
                              void* d_out, int out_size) {
    const float* x   = (const float*)d_in[0];   // [8,1024,128]
    const int*   adj = (const int*)d_in[1];     // [8,1024,1024]
    const float* W   = (const float*)d_in[2];   // [128,256]
    const float* a   = (const float*)d_in[3];   // [128]
    float* out = (float*)d_out;                 // [8,1024,256]

    cudaFuncSetAttribute(k_gemm, cudaFuncAttributeMaxDynamicSharedMemorySize,
                         G_SM_TOTAL);
    cudaFuncSetAttribute(k_aggr, cudaFuncAttributeMaxDynamicSharedMemorySize,
                         SM_TOTAL);

    k_gemm<<<dim3(BN / 128, NH), 256, G_SM_TOTAL>>>(x, W, a);
    k_aggr<<<dim3(32, BB), 256, SM_TOTAL>>>(adj, out);
}